// round 8
// baseline (speedup 1.0000x reference)
#include <cuda_runtime.h>

#define N_NODES 100000
#define E_MAX   1600000
#define D_IN    128
#define D_H     64
#define D_OUT   16
#define SLOT    80          // fixed CSR slots per node (Poisson(16): P(deg>=80)~1e-28)

// ---- packed f32x2 helpers (sm_103a dual-lane fp32 pipe) ----
#define FFMA2(d, a, b, c) \
    asm("fma.rn.f32x2 %0, %1, %2, %3;" : "=l"(d) : "l"(a), "l"(b), "l"(c))
#define FADD2(d, a, b) \
    asm("add.rn.f32x2 %0, %1, %2;" : "=l"(d) : "l"(a), "l"(b))

__device__ __forceinline__ unsigned long long pack2(float lo, float hi) {
    unsigned long long r;
    asm("mov.b64 %0, {%1, %2};" : "=l"(r) : "f"(lo), "f"(hi));
    return r;
}
__device__ __forceinline__ void unpack2(unsigned long long v, float& lo, float& hi) {
    asm("mov.b64 {%0, %1}, %2;" : "=f"(lo), "=f"(hi) : "l"(v));
}

// ---- scratch (__device__ globals: allocation-free rule) ----
// g_cnt arrives zeroed (zero-init at load; re-zeroed by k_agg2 every run).
__device__ int   g_cnt[N_NODES];
__device__ int   g_csr[(size_t)N_NODES * SLOT];
__device__ float g_hs1[(size_t)N_NODES * D_H];    // x@W1, scaled in-place by k_scale
__device__ float g_hs2[(size_t)N_NODES * D_OUT];  // dinv-scaled layer-2 features

// ================= fat kernel: CSR build + layer-1 GEMM, interleaved =================
// gemm writes UNSCALED hs1 (no g_cnt read) -> build & gemm blocks independent.
// 64x64 gemm tile keeps regs low so the latency-bound build blocks get occupancy.

__device__ __forceinline__ void build_body(const int* __restrict__ src,
                                           const int* __restrict__ dst,
                                           int E, int bid) {
    int b = (bid * 256 + threadIdx.x) * 4;
    if (b + 3 < E && ((E & 3) == 0)) {
        int4 s = *(const int4*)&src[b];
        int4 d = *(const int4*)&dst[b];
        int r0 = atomicAdd(&g_cnt[d.x], 1);
        int r1 = atomicAdd(&g_cnt[d.y], 1);
        int r2 = atomicAdd(&g_cnt[d.z], 1);
        int r3 = atomicAdd(&g_cnt[d.w], 1);
        if (r0 < SLOT) g_csr[(size_t)d.x * SLOT + r0] = s.x;
        if (r1 < SLOT) g_csr[(size_t)d.y * SLOT + r1] = s.y;
        if (r2 < SLOT) g_csr[(size_t)d.z * SLOT + r2] = s.z;
        if (r3 < SLOT) g_csr[(size_t)d.w * SLOT + r3] = s.w;
    } else {
#pragma unroll
        for (int j = 0; j < 4; j++)
            if (b + j < E) {
                int d = dst[b + j];
                int r = atomicAdd(&g_cnt[d], 1);
                if (r < SLOT) g_csr[(size_t)d * SLOT + r] = src[b + j];
            }
    }
}

__global__ __launch_bounds__(256) void k_build_gemm(const float* __restrict__ x,
                                                    const float* __restrict__ W1,
                                                    const int* __restrict__ src,
                                                    const int* __restrict__ dst,
                                                    int E, int gb, int total) {
    // Bresenham interleave: spread gb gemm blocks uniformly over [0,total)
    const int bid  = blockIdx.x;
    const int g_lo = (int)(((long long)bid * gb) / total);
    const int g_hi = (int)(((long long)(bid + 1) * gb) / total);

    if (g_hi == g_lo) {                 // ---- build block ----
        build_body(src, dst, E, bid - g_lo);
        return;
    }

    // ---- gemm block: 64x64 tile, BK=32, 4x4 thread tile, FFMA2 ----
    __shared__ unsigned long long Xs2[32][33];  // [m-pair][k]
    __shared__ unsigned long long Wd [32][68];  // dup (w,w), stride-17 layout

    const int tid  = threadIdx.x;
    const int tx   = tid & 15;      // 4 output cols
    const int ty   = tid >> 4;      // 16 groups x 4 rows = 2 row-pairs each
    const int row0 = g_lo * 64;

    unsigned long long acc[2][4];
#pragma unroll
    for (int i = 0; i < 2; i++)
#pragma unroll
        for (int j = 0; j < 4; j++) acc[i][j] = 0ull;

    for (int k0 = 0; k0 < D_IN; k0 += 32) {
#pragma unroll
        for (int l = 0; l < 4; l++) {          // X: 32 m-pairs x 32 k
            int idx = tid + l * 256;
            int k = idx & 31, mp = idx >> 5;
            int rA = row0 + 2 * mp;
            float lo = (rA     < N_NODES) ? x[(size_t)rA * D_IN + k0 + k]       : 0.f;
            float hi = (rA + 1 < N_NODES) ? x[(size_t)(rA + 1) * D_IN + k0 + k] : 0.f;
            Xs2[mp][k] = pack2(lo, hi);
        }
#pragma unroll
        for (int l = 0; l < 8; l++) {          // W: 32k x 64n duplicated-pack
            int idx = tid + l * 256;
            int k = idx >> 6, n = idx & 63;
            float w = W1[(size_t)(k0 + k) * D_H + n];
            Wd[k][(n & 3) * 17 + (n >> 2)] = pack2(w, w);
        }
        __syncthreads();
#pragma unroll
        for (int k = 0; k < 32; k++) {
            unsigned long long A0 = Xs2[2 * ty    ][k];
            unsigned long long A1 = Xs2[2 * ty + 1][k];
            unsigned long long b0 = Wd[k][0 * 17 + tx];
            unsigned long long b1 = Wd[k][1 * 17 + tx];
            unsigned long long b2 = Wd[k][2 * 17 + tx];
            unsigned long long b3 = Wd[k][3 * 17 + tx];
            FFMA2(acc[0][0], A0, b0, acc[0][0]);
            FFMA2(acc[0][1], A0, b1, acc[0][1]);
            FFMA2(acc[0][2], A0, b2, acc[0][2]);
            FFMA2(acc[0][3], A0, b3, acc[0][3]);
            FFMA2(acc[1][0], A1, b0, acc[1][0]);
            FFMA2(acc[1][1], A1, b1, acc[1][1]);
            FFMA2(acc[1][2], A1, b2, acc[1][2]);
            FFMA2(acc[1][3], A1, b3, acc[1][3]);
        }
        __syncthreads();
    }

#pragma unroll
    for (int i = 0; i < 2; i++) {
        float r0[4], r1[4];
#pragma unroll
        for (int j = 0; j < 4; j++) unpack2(acc[i][j], r0[j], r1[j]);
        int rowA = row0 + ty * 4 + 2 * i;
        int rowB = rowA + 1;
        if (rowA < N_NODES) {
            float4 v = {r0[0], r0[1], r0[2], r0[3]};
            *(float4*)&g_hs1[(size_t)rowA * D_H + tx * 4] = v;
        }
        if (rowB < N_NODES) {
            float4 v = {r1[0], r1[1], r1[2], r1[3]};
            *(float4*)&g_hs1[(size_t)rowB * D_H + tx * 4] = v;
        }
    }
}

// ================= scale pass: hs1[n] *= rsqrt(deg_n) (coalesced) =================

__global__ __launch_bounds__(256) void k_scale() {
    int t = blockIdx.x * blockDim.x + threadIdx.x;     // one float4 per thread
    int n = t >> 4;
    if (n >= N_NODES) return;
    float di = rsqrtf((float)g_cnt[n] + 1.0f);         // broadcast within 16 threads
    float4* p = (float4*)&g_hs1[(size_t)t * 4];
    float4 v = *p;
    v.x *= di; v.y *= di; v.z *= di; v.w *= di;
    *p = v;
}

// ================= fused layer-1 aggregation + relu + GEMV(W2) =================
// 16 nodes x 16 lanes per block; hs1 rows pre-scaled -> pure FADD2 gather.

__global__ __launch_bounds__(256) void k_agg_node(const float* __restrict__ b1,
                                                  const float* __restrict__ W2) {
    __shared__ float sh [16][68];
    __shared__ float W2t[16][68];   // W2t[j][k] = W2[k][j]

    const int tid  = threadIdx.x;
    const int part = tid & 15;
    const int nl   = tid >> 4;
    const int n    = blockIdx.x * 16 + nl;
    const int lane = tid & 31;
    const int gb   = lane & 16;
    const unsigned gmask = 0xFFFFu << gb;

#pragma unroll
    for (int idx = tid; idx < D_H * D_OUT; idx += 256) {
        int k = idx >> 4, j = idx & 15;
        W2t[j][k] = W2[idx];
    }

    const int cnt_n = g_cnt[n];
    int cnt = cnt_n > SLOT ? SLOT : cnt_n;
    const float dn = rsqrtf((float)cnt_n + 1.0f);
    const size_t off = (size_t)n * SLOT;

    const ulonglong2* base = (const ulonglong2*)g_hs1;
    ulonglong2 acc = base[(size_t)n * 16 + part];      // self-loop (pre-scaled)

    for (int i = 0; i < cnt; i += 16) {
        int idx = (i + part < cnt) ? g_csr[off + i + part] : 0;
#pragma unroll
        for (int j = 0; j < 16; j++) {
            int s = __shfl_sync(gmask, idx, gb + j);
            if (i + j < cnt) {
                ulonglong2 v = base[(size_t)s * 16 + part];
                FADD2(acc.x, acc.x, v.x);
                FADD2(acc.y, acc.y, v.y);
            }
        }
    }

    float a0, a1, a2, a3;
    unpack2(acc.x, a0, a1);
    unpack2(acc.y, a2, a3);
    float4 bb = *(const float4*)&b1[part * 4];
    float4 r;
    r.x = fmaxf(fmaf(dn, a0, bb.x), 0.f);
    r.y = fmaxf(fmaf(dn, a1, bb.y), 0.f);
    r.z = fmaxf(fmaf(dn, a2, bb.z), 0.f);
    r.w = fmaxf(fmaf(dn, a3, bb.w), 0.f);
    *(float4*)&sh[nl][part * 4] = r;
    __syncthreads();

    float o = 0.f;
#pragma unroll
    for (int k4 = 0; k4 < D_H / 4; k4++) {
        float4 v4 = *(const float4*)&sh [nl]  [k4 * 4];
        float4 w4 = *(const float4*)&W2t[part][k4 * 4];
        o = fmaf(v4.x, w4.x, o);
        o = fmaf(v4.y, w4.y, o);
        o = fmaf(v4.z, w4.z, o);
        o = fmaf(v4.w, w4.w, o);
    }
    g_hs2[(size_t)n * D_OUT + part] = o * dn;   // pre-scaled by dinv_n
}

// ================= layer-2 aggregation + epilogue; resets g_cnt =================
// 4 lanes per node; hs2 rows already dinv-scaled -> plain adds.

__global__ __launch_bounds__(256) void k_agg2(const float* __restrict__ b2,
                                              float* __restrict__ out) {
    long long t = (long long)blockIdx.x * blockDim.x + threadIdx.x;
    int n = (int)(t >> 2);
    const int valid = (n < N_NODES);
    if (!valid) n = N_NODES - 1;        // clamp (shfl safety)
    const int part = (int)(t & 3);
    const int lane = threadIdx.x & 31;
    const int gb4  = lane & ~3;
    const unsigned gmask = 0xFu << gb4;

    const int rawcnt = g_cnt[n];
    int cnt = rawcnt > SLOT ? SLOT : rawcnt;
    const size_t off = (size_t)n * SLOT;

    const ulonglong2* base = (const ulonglong2*)g_hs2;
    ulonglong2 acc = base[(size_t)n * 4 + part];           // self-loop term

    for (int i = 0; i < cnt; i += 8) {
        int i0 = i + part;
        int i1 = i + 4 + part;
        int idxA = (i0 < cnt) ? g_csr[off + i0] : 0;
        int idxB = (i1 < cnt) ? g_csr[off + i1] : 0;
#pragma unroll
        for (int j = 0; j < 4; j++) {
            int s = __shfl_sync(gmask, idxA, gb4 + j);
            if (i + j < cnt) {
                ulonglong2 v = base[(size_t)s * 4 + part];
                FADD2(acc.x, acc.x, v.x);
                FADD2(acc.y, acc.y, v.y);
            }
        }
#pragma unroll
        for (int j = 0; j < 4; j++) {
            int s = __shfl_sync(gmask, idxB, gb4 + j);
            if (i + 4 + j < cnt) {
                ulonglong2 v = base[(size_t)s * 4 + part];
                FADD2(acc.x, acc.x, v.x);
                FADD2(acc.y, acc.y, v.y);
            }
        }
    }

    if (valid && part == 0) g_cnt[n] = 0;   // reset for next run (after reads)

    if (valid) {
        float a0, a1, a2, a3;
        unpack2(acc.x, a0, a1);
        unpack2(acc.y, a2, a3);
        float di = rsqrtf((float)rawcnt + 1.0f);
        float4 bb = *(const float4*)&b2[part * 4];
        float4 o = {fmaf(di, a0, bb.x), fmaf(di, a1, bb.y),
                    fmaf(di, a2, bb.z), fmaf(di, a3, bb.w)};
        *(float4*)&out[(size_t)n * D_OUT + part * 4] = o;
    }
}

// ================= launch =================

extern "C" void kernel_launch(void* const* d_in, const int* in_sizes, int n_in,
                              void* d_out, int out_size) {
    const float* x  = (const float*)d_in[0];
    const int*   ei = (const int*)  d_in[1];
    const float* W1 = (const float*)d_in[2];
    const float* b1 = (const float*)d_in[3];
    const float* W2 = (const float*)d_in[4];
    const float* b2 = (const float*)d_in[5];
    const int E = in_sizes[1] / 2;
    const int* src = ei;
    const int* dst = ei + E;

    const int gemm_blocks  = (N_NODES + 63) / 64;          // 1563
    const int build_blocks = (E / 4 + 255) / 256 + 1;      // 1564
    const int total        = gemm_blocks + build_blocks;

    k_build_gemm<<<total, 256>>>(x, W1, src, dst, E, gemm_blocks, total);
    k_scale     <<<(N_NODES * 16 + 255) / 256, 256>>>();
    k_agg_node  <<<N_NODES / 16, 256>>>(b1, W2);            // 100000/16 exact
    k_agg2      <<<(N_NODES * 4 + 255) / 256, 256>>>(b2, (float*)d_out);
}

// round 9
// speedup vs baseline: 1.1377x; 1.1377x over previous
#include <cuda_runtime.h>

#define N_NODES 100000
#define E_MAX   1600000
#define D_IN    128
#define D_H     64
#define D_OUT   16
#define SLOT    80          // fixed CSR slots per node (Poisson(16): P(deg>=80)~1e-28)

// ---- packed f32x2 helpers (sm_103a dual-lane fp32 pipe) ----
#define FFMA2(d, a, b, c) \
    asm("fma.rn.f32x2 %0, %1, %2, %3;" : "=l"(d) : "l"(a), "l"(b), "l"(c))
#define FADD2(d, a, b) \
    asm("add.rn.f32x2 %0, %1, %2;" : "=l"(d) : "l"(a), "l"(b))

__device__ __forceinline__ unsigned long long pack2(float lo, float hi) {
    unsigned long long r;
    asm("mov.b64 %0, {%1, %2};" : "=l"(r) : "f"(lo), "f"(hi));
    return r;
}
__device__ __forceinline__ void unpack2(unsigned long long v, float& lo, float& hi) {
    asm("mov.b64 {%0, %1}, %2;" : "=f"(lo), "=f"(hi) : "l"(v));
}

// ---- scratch (__device__ globals: allocation-free rule) ----
// g_cnt arrives zeroed (zero-init at load; re-zeroed by k_agg2 every run).
__device__ int   g_cnt[N_NODES];
__device__ int   g_csr[(size_t)N_NODES * SLOT];
__device__ float g_hs1[(size_t)N_NODES * D_H];    // x@W1, scaled in-place by k_scale
__device__ float g_hs2[(size_t)N_NODES * D_OUT];  // dinv-scaled layer-2 features

// ================= fused kernel: per-block edge chunk + 128x64 GEMM tile =================
// Every block first scatters 2048 edges into the slotted CSR (warps stall once
// on ATOMG; hidden by sibling warps' FFMA2), then computes its gemm tile.
// gemm writes UNSCALED hs1 (no g_cnt dependency).

#define EDGES_PER_BLOCK 2048

__global__ __launch_bounds__(256, 3) void k_build_gemm(const float* __restrict__ x,
                                                       const float* __restrict__ W1,
                                                       const int* __restrict__ src,
                                                       const int* __restrict__ dst,
                                                       int E) {
    const int tid = threadIdx.x;

    // ---- build phase: 8 edges/thread in two coalesced int4 batches ----
    {
        const int base = blockIdx.x * EDGES_PER_BLOCK;
#pragma unroll
        for (int half = 0; half < 2; half++) {
            int b = base + half * 1024 + tid * 4;
            if (b + 3 < E) {
                int4 s = *(const int4*)&src[b];
                int4 d = *(const int4*)&dst[b];
                int r0 = atomicAdd(&g_cnt[d.x], 1);
                int r1 = atomicAdd(&g_cnt[d.y], 1);
                int r2 = atomicAdd(&g_cnt[d.z], 1);
                int r3 = atomicAdd(&g_cnt[d.w], 1);
                if (r0 < SLOT) g_csr[(size_t)d.x * SLOT + r0] = s.x;
                if (r1 < SLOT) g_csr[(size_t)d.y * SLOT + r1] = s.y;
                if (r2 < SLOT) g_csr[(size_t)d.z * SLOT + r2] = s.z;
                if (r3 < SLOT) g_csr[(size_t)d.w * SLOT + r3] = s.w;
            } else {
#pragma unroll
                for (int j = 0; j < 4; j++)
                    if (b + j < E) {
                        int d = dst[b + j];
                        int r = atomicAdd(&g_cnt[d], 1);
                        if (r < SLOT) g_csr[(size_t)d * SLOT + r] = src[b + j];
                    }
            }
        }
    }

    // ---- gemm phase: 128x64 tile, BK=32, 8x4 thread tile, FFMA2 ----
    __shared__ unsigned long long Xs2[64][33];  // [m-pair][k], broadcast LDS.64
    __shared__ unsigned long long Wd [32][68];  // dup (w,w), stride-17 layout

    const int tx   = tid & 15;      // 4 output cols
    const int ty   = tid >> 4;      // 4 row-pairs (8 rows)
    const int row0 = blockIdx.x * 128;

    unsigned long long acc[4][4];
#pragma unroll
    for (int i = 0; i < 4; i++)
#pragma unroll
        for (int j = 0; j < 4; j++) acc[i][j] = 0ull;

    for (int k0 = 0; k0 < D_IN; k0 += 32) {
#pragma unroll
        for (int l = 0; l < 8; l++) {          // X: 64 m-pairs x 32 k
            int idx = tid + l * 256;
            int k = idx & 31, mp = idx >> 5;
            int rA = row0 + 2 * mp;
            float lo = (rA     < N_NODES) ? x[(size_t)rA * D_IN + k0 + k]       : 0.f;
            float hi = (rA + 1 < N_NODES) ? x[(size_t)(rA + 1) * D_IN + k0 + k] : 0.f;
            Xs2[mp][k] = pack2(lo, hi);
        }
#pragma unroll
        for (int l = 0; l < 8; l++) {          // W: 32k x 64n duplicated-pack
            int idx = tid + l * 256;
            int k = idx >> 6, n = idx & 63;
            float w = W1[(size_t)(k0 + k) * D_H + n];
            Wd[k][(n & 3) * 17 + (n >> 2)] = pack2(w, w);
        }
        __syncthreads();
#pragma unroll
        for (int k = 0; k < 32; k++) {
            unsigned long long A0 = Xs2[ty * 4 + 0][k];
            unsigned long long A1 = Xs2[ty * 4 + 1][k];
            unsigned long long A2 = Xs2[ty * 4 + 2][k];
            unsigned long long A3 = Xs2[ty * 4 + 3][k];
            unsigned long long b0 = Wd[k][0 * 17 + tx];
            unsigned long long b1 = Wd[k][1 * 17 + tx];
            unsigned long long b2 = Wd[k][2 * 17 + tx];
            unsigned long long b3 = Wd[k][3 * 17 + tx];
            FFMA2(acc[0][0], A0, b0, acc[0][0]);
            FFMA2(acc[0][1], A0, b1, acc[0][1]);
            FFMA2(acc[0][2], A0, b2, acc[0][2]);
            FFMA2(acc[0][3], A0, b3, acc[0][3]);
            FFMA2(acc[1][0], A1, b0, acc[1][0]);
            FFMA2(acc[1][1], A1, b1, acc[1][1]);
            FFMA2(acc[1][2], A1, b2, acc[1][2]);
            FFMA2(acc[1][3], A1, b3, acc[1][3]);
            FFMA2(acc[2][0], A2, b0, acc[2][0]);
            FFMA2(acc[2][1], A2, b1, acc[2][1]);
            FFMA2(acc[2][2], A2, b2, acc[2][2]);
            FFMA2(acc[2][3], A2, b3, acc[2][3]);
            FFMA2(acc[3][0], A3, b0, acc[3][0]);
            FFMA2(acc[3][1], A3, b1, acc[3][1]);
            FFMA2(acc[3][2], A3, b2, acc[3][2]);
            FFMA2(acc[3][3], A3, b3, acc[3][3]);
        }
        __syncthreads();
    }

#pragma unroll
    for (int i = 0; i < 4; i++) {
        float r0[4], r1[4];
#pragma unroll
        for (int j = 0; j < 4; j++) unpack2(acc[i][j], r0[j], r1[j]);
        int rowA = row0 + (ty * 4 + i) * 2;
        int rowB = rowA + 1;
        if (rowA < N_NODES) {
            float4 v = {r0[0], r0[1], r0[2], r0[3]};
            *(float4*)&g_hs1[(size_t)rowA * D_H + tx * 4] = v;
        }
        if (rowB < N_NODES) {
            float4 v = {r1[0], r1[1], r1[2], r1[3]};
            *(float4*)&g_hs1[(size_t)rowB * D_H + tx * 4] = v;
        }
    }
}

// ================= scale pass: hs1[n] *= rsqrt(deg_n) (coalesced) =================

__global__ __launch_bounds__(256) void k_scale() {
    int t = blockIdx.x * blockDim.x + threadIdx.x;     // one float4 per thread
    int n = t >> 4;
    if (n >= N_NODES) return;
    float di = rsqrtf((float)g_cnt[n] + 1.0f);         // broadcast within 16 threads
    float4* p = (float4*)&g_hs1[(size_t)t * 4];
    float4 v = *p;
    v.x *= di; v.y *= di; v.z *= di; v.w *= di;
    *p = v;
}

// ================= fused layer-1 aggregation + relu + GEMV(W2) =================
// 16 nodes x 16 lanes per block; hs1 rows pre-scaled -> pure FADD2 gather.

__global__ __launch_bounds__(256) void k_agg_node(const float* __restrict__ b1,
                                                  const float* __restrict__ W2) {
    __shared__ float sh [16][68];
    __shared__ float W2t[16][68];   // W2t[j][k] = W2[k][j]

    const int tid  = threadIdx.x;
    const int part = tid & 15;
    const int nl   = tid >> 4;
    const int n    = blockIdx.x * 16 + nl;
    const int lane = tid & 31;
    const int gb   = lane & 16;
    const unsigned gmask = 0xFFFFu << gb;

#pragma unroll
    for (int idx = tid; idx < D_H * D_OUT; idx += 256) {
        int k = idx >> 4, j = idx & 15;
        W2t[j][k] = W2[idx];
    }

    const int cnt_n = g_cnt[n];
    int cnt = cnt_n > SLOT ? SLOT : cnt_n;
    const float dn = rsqrtf((float)cnt_n + 1.0f);
    const size_t off = (size_t)n * SLOT;

    const ulonglong2* base = (const ulonglong2*)g_hs1;
    ulonglong2 acc = base[(size_t)n * 16 + part];      // self-loop (pre-scaled)

    for (int i = 0; i < cnt; i += 16) {
        int idx = (i + part < cnt) ? g_csr[off + i + part] : 0;
#pragma unroll
        for (int j = 0; j < 16; j++) {
            int s = __shfl_sync(gmask, idx, gb + j);
            if (i + j < cnt) {
                ulonglong2 v = base[(size_t)s * 16 + part];
                FADD2(acc.x, acc.x, v.x);
                FADD2(acc.y, acc.y, v.y);
            }
        }
    }

    float a0, a1, a2, a3;
    unpack2(acc.x, a0, a1);
    unpack2(acc.y, a2, a3);
    float4 bb = *(const float4*)&b1[part * 4];
    float4 r;
    r.x = fmaxf(fmaf(dn, a0, bb.x), 0.f);
    r.y = fmaxf(fmaf(dn, a1, bb.y), 0.f);
    r.z = fmaxf(fmaf(dn, a2, bb.z), 0.f);
    r.w = fmaxf(fmaf(dn, a3, bb.w), 0.f);
    *(float4*)&sh[nl][part * 4] = r;
    __syncthreads();

    float o = 0.f;
#pragma unroll
    for (int k4 = 0; k4 < D_H / 4; k4++) {
        float4 v4 = *(const float4*)&sh [nl]  [k4 * 4];
        float4 w4 = *(const float4*)&W2t[part][k4 * 4];
        o = fmaf(v4.x, w4.x, o);
        o = fmaf(v4.y, w4.y, o);
        o = fmaf(v4.z, w4.z, o);
        o = fmaf(v4.w, w4.w, o);
    }
    g_hs2[(size_t)n * D_OUT + part] = o * dn;   // pre-scaled by dinv_n
}

// ================= layer-2 aggregation + epilogue; resets g_cnt =================
// 4 lanes per node; hs2 rows already dinv-scaled -> plain adds.

__global__ __launch_bounds__(256) void k_agg2(const float* __restrict__ b2,
                                              float* __restrict__ out) {
    long long t = (long long)blockIdx.x * blockDim.x + threadIdx.x;
    int n = (int)(t >> 2);
    const int valid = (n < N_NODES);
    if (!valid) n = N_NODES - 1;        // clamp (shfl safety)
    const int part = (int)(t & 3);
    const int lane = threadIdx.x & 31;
    const int gb4  = lane & ~3;
    const unsigned gmask = 0xFu << gb4;

    const int rawcnt = g_cnt[n];
    int cnt = rawcnt > SLOT ? SLOT : rawcnt;
    const size_t off = (size_t)n * SLOT;

    const ulonglong2* base = (const ulonglong2*)g_hs2;
    ulonglong2 acc = base[(size_t)n * 4 + part];           // self-loop term

    for (int i = 0; i < cnt; i += 8) {
        int i0 = i + part;
        int i1 = i + 4 + part;
        int idxA = (i0 < cnt) ? g_csr[off + i0] : 0;
        int idxB = (i1 < cnt) ? g_csr[off + i1] : 0;
#pragma unroll
        for (int j = 0; j < 4; j++) {
            int s = __shfl_sync(gmask, idxA, gb4 + j);
            if (i + j < cnt) {
                ulonglong2 v = base[(size_t)s * 4 + part];
                FADD2(acc.x, acc.x, v.x);
                FADD2(acc.y, acc.y, v.y);
            }
        }
#pragma unroll
        for (int j = 0; j < 4; j++) {
            int s = __shfl_sync(gmask, idxB, gb4 + j);
            if (i + 4 + j < cnt) {
                ulonglong2 v = base[(size_t)s * 4 + part];
                FADD2(acc.x, acc.x, v.x);
                FADD2(acc.y, acc.y, v.y);
            }
        }
    }

    if (valid && part == 0) g_cnt[n] = 0;   // reset for next run (after reads)

    if (valid) {
        float a0, a1, a2, a3;
        unpack2(acc.x, a0, a1);
        unpack2(acc.y, a2, a3);
        float di = rsqrtf((float)rawcnt + 1.0f);
        float4 bb = *(const float4*)&b2[part * 4];
        float4 o = {fmaf(di, a0, bb.x), fmaf(di, a1, bb.y),
                    fmaf(di, a2, bb.z), fmaf(di, a3, bb.w)};
        *(float4*)&out[(size_t)n * D_OUT + part * 4] = o;
    }
}

// ================= launch =================

extern "C" void kernel_launch(void* const* d_in, const int* in_sizes, int n_in,
                              void* d_out, int out_size) {
    const float* x  = (const float*)d_in[0];
    const int*   ei = (const int*)  d_in[1];
    const float* W1 = (const float*)d_in[2];
    const float* b1 = (const float*)d_in[3];
    const float* W2 = (const float*)d_in[4];
    const float* b2 = (const float*)d_in[5];
    const int E = in_sizes[1] / 2;
    const int* src = ei;
    const int* dst = ei + E;

    const int gemm_blocks = (N_NODES + 127) / 128;   // 782
    // 782 blocks x 2048 edges = 1,601,536 >= E — every edge covered (guarded).

    k_build_gemm<<<gemm_blocks, 256>>>(x, W1, src, dst, E);
    k_scale     <<<(N_NODES * 16 + 255) / 256, 256>>>();
    k_agg_node  <<<N_NODES / 16, 256>>>(b1, W2);      // 100000/16 exact
    k_agg2      <<<(N_NODES * 4 + 255) / 256, 256>>>(b2, (float*)d_out);
}

// round 11
// speedup vs baseline: 1.2435x; 1.0929x over previous
#include <cuda_runtime.h>
#include <cuda_bf16.h>
#include <cstdint>

#define N_NODES 100000
#define E_MAX   1600000
#define D_IN    128
#define D_H     64
#define D_OUT   16
#define SLOT    80

// ---- packed f32x2 helpers (aggregators) ----
#define FADD2(d, a, b) \
    asm("add.rn.f32x2 %0, %1, %2;" : "=l"(d) : "l"(a), "l"(b))
__device__ __forceinline__ void unpack2(unsigned long long v, float& lo, float& hi) {
    asm("mov.b64 {%0, %1}, %2;" : "=f"(lo), "=f"(hi) : "l"(v));
}

// ---- warp-level bf16 mma (baseline PTX, works on compute_103) ----
__device__ __forceinline__ void mma_bf16(float c[4],
                                         uint32_t a0, uint32_t a1, uint32_t a2, uint32_t a3,
                                         uint32_t b0, uint32_t b1) {
    asm volatile(
        "mma.sync.aligned.m16n8k16.row.col.f32.bf16.bf16.f32 "
        "{%0,%1,%2,%3}, {%4,%5,%6,%7}, {%8,%9}, {%0,%1,%2,%3};"
        : "+f"(c[0]), "+f"(c[1]), "+f"(c[2]), "+f"(c[3])
        : "r"(a0), "r"(a1), "r"(a2), "r"(a3), "r"(b0), "r"(b1));
}

__device__ __forceinline__ void split_bf16(float f, unsigned& hb, unsigned& lb) {
    __nv_bfloat16 h = __float2bfloat16(f);
    float r = f - __bfloat162float(h);
    hb = (unsigned)__bfloat16_as_ushort(h);
    lb = (unsigned)__bfloat16_as_ushort(__float2bfloat16(r));
}

// ---- scratch ----
__device__ int   g_cnt[N_NODES];
__device__ int   g_csr[(size_t)N_NODES * SLOT];
__device__ float g_hs1[(size_t)N_NODES * D_H];
__device__ float g_hs2[(size_t)N_NODES * D_OUT];

// dynamic smem layout (bytes); A/B tiles bf16, row stride 136 elems = 272B
// 272B = 68 banks == 4 (mod 32): frag addresses (4*gid + tig) cover all banks.
#define A_STRIDE 272
#define SM_AH 0                       // 128 x 136 bf16 = 34816
#define SM_AL 34816                   // 34816
#define SM_BH 69632                   // 64 x 136 bf16 = 17408 (n-major)
#define SM_BL 87040                   // 17408
#define SMEM_TOTAL 104448

// ============ fused kernel: CSR build + HMMA bf16-split GEMM ============

__global__ __launch_bounds__(256, 2) void k_fused(const float* __restrict__ x,
                                                  const float* __restrict__ W1,
                                                  const int* __restrict__ src,
                                                  const int* __restrict__ dst, int E) {
    extern __shared__ __align__(16) char smem[];
    const int tid  = threadIdx.x;
    const int wid  = tid >> 5;
    const int lane = tid & 31;
    const int row0 = blockIdx.x * 128;

    // ---- build phase: 2048 edges/block ----
    {
        const int base = blockIdx.x * 2048;
#pragma unroll
        for (int half = 0; half < 2; half++) {
            int b = base + half * 1024 + tid * 4;
            if (b + 3 < E) {
                int4 s = *(const int4*)&src[b];
                int4 d = *(const int4*)&dst[b];
                int r0 = atomicAdd(&g_cnt[d.x], 1);
                int r1 = atomicAdd(&g_cnt[d.y], 1);
                int r2 = atomicAdd(&g_cnt[d.z], 1);
                int r3 = atomicAdd(&g_cnt[d.w], 1);
                if (r0 < SLOT) g_csr[(size_t)d.x * SLOT + r0] = s.x;
                if (r1 < SLOT) g_csr[(size_t)d.y * SLOT + r1] = s.y;
                if (r2 < SLOT) g_csr[(size_t)d.z * SLOT + r2] = s.z;
                if (r3 < SLOT) g_csr[(size_t)d.w * SLOT + r3] = s.w;
            } else {
#pragma unroll
                for (int j = 0; j < 4; j++)
                    if (b + j < E) {
                        int d = dst[b + j];
                        int r = atomicAdd(&g_cnt[d], 1);
                        if (r < SLOT) g_csr[(size_t)d * SLOT + r] = src[b + j];
                    }
            }
        }
    }

    // ---- load X tile (128 x 128 f32) -> Ah/Al bf16 (row-major, stride 272B) ----
#pragma unroll
    for (int i = 0; i < 16; i++) {
        int idx4 = tid + i * 256;            // 0..4095 float4s
        int row = idx4 >> 5, c4 = idx4 & 31;
        int grow = row0 + row;
        float4 v = make_float4(0.f, 0.f, 0.f, 0.f);
        if (grow < N_NODES) v = *(const float4*)&x[(size_t)grow * D_IN + c4 * 4];
        unsigned h0, l0, h1, l1, h2, l2, h3, l3;
        split_bf16(v.x, h0, l0); split_bf16(v.y, h1, l1);
        split_bf16(v.z, h2, l2); split_bf16(v.w, h3, l3);
        uint2 hv = make_uint2(h0 | (h1 << 16), h2 | (h3 << 16));
        uint2 lv = make_uint2(l0 | (l1 << 16), l2 | (l3 << 16));
        int off = row * A_STRIDE + c4 * 8;   // 8B per float4 (4 bf16)
        *(uint2*)(smem + SM_AH + off) = hv;
        *(uint2*)(smem + SM_AL + off) = lv;
    }

    // ---- W1 (128k x 64n) -> Bh/Bl n-major: B[n][k], stride 272B ----
#pragma unroll
    for (int e = 0; e < 32; e++) {
        int idx = tid + e * 256;             // coalesced over n
        int k = idx >> 6, n = idx & 63;
        unsigned hb, lb;
        split_bf16(W1[idx], hb, lb);
        int off = n * A_STRIDE + k * 2;
        *(unsigned short*)(smem + SM_BH + off) = (unsigned short)hb;
        *(unsigned short*)(smem + SM_BL + off) = (unsigned short)lb;
    }
    __syncthreads();

    // ---- mma mainloop: each warp owns rows [wid*16, wid*16+16) ----
    const int gid = lane >> 2;               // 0..7
    const int tig = lane & 3;                // 0..3
    const int ra = wid * 16 + gid;           // rows for a0/a2, c0/c1
    const int rb = ra + 8;                   // rows for a1/a3, c2/c3

    float c[8][4];
#pragma unroll
    for (int nt = 0; nt < 8; nt++)
#pragma unroll
        for (int j = 0; j < 4; j++) c[nt][j] = 0.f;

    const char* pAH = smem + SM_AH;
    const char* pAL = smem + SM_AL;
    const char* pBH = smem + SM_BH;
    const char* pBL = smem + SM_BL;

#pragma unroll 2
    for (int ks = 0; ks < 8; ks++) {
        const int kb = ks * 32 + tig * 4;    // byte offset of k-pair (k0 = ks*16)
        uint32_t ah0 = *(const uint32_t*)(pAH + ra * A_STRIDE + kb);
        uint32_t ah1 = *(const uint32_t*)(pAH + rb * A_STRIDE + kb);
        uint32_t ah2 = *(const uint32_t*)(pAH + ra * A_STRIDE + kb + 16);
        uint32_t ah3 = *(const uint32_t*)(pAH + rb * A_STRIDE + kb + 16);
        uint32_t al0 = *(const uint32_t*)(pAL + ra * A_STRIDE + kb);
        uint32_t al1 = *(const uint32_t*)(pAL + rb * A_STRIDE + kb);
        uint32_t al2 = *(const uint32_t*)(pAL + ra * A_STRIDE + kb + 16);
        uint32_t al3 = *(const uint32_t*)(pAL + rb * A_STRIDE + kb + 16);
#pragma unroll
        for (int nt = 0; nt < 8; nt++) {
            const int brow = nt * 8 + gid;
            uint32_t bh0 = *(const uint32_t*)(pBH + brow * A_STRIDE + kb);
            uint32_t bh1 = *(const uint32_t*)(pBH + brow * A_STRIDE + kb + 16);
            uint32_t bl0 = *(const uint32_t*)(pBL + brow * A_STRIDE + kb);
            uint32_t bl1 = *(const uint32_t*)(pBL + brow * A_STRIDE + kb + 16);
            mma_bf16(c[nt], ah0, ah1, ah2, ah3, bh0, bh1);   // hi*hi
            mma_bf16(c[nt], ah0, ah1, ah2, ah3, bl0, bl1);   // hi*lo
            mma_bf16(c[nt], al0, al1, al2, al3, bh0, bh1);   // lo*hi
        }
    }
    __syncwarp();

    // ---- stage D to smem (reuse AH region as float rows, stride 272B) ----
    float* Ds = (float*)(smem + SM_AH);
#pragma unroll
    for (int nt = 0; nt < 8; nt++) {
        int cb = nt * 8 + tig * 2;           // f32 column
        *(float2*)&Ds[ra * (A_STRIDE / 4) + cb] = make_float2(c[nt][0], c[nt][1]);
        *(float2*)&Ds[rb * (A_STRIDE / 4) + cb] = make_float2(c[nt][2], c[nt][3]);
    }
    __syncthreads();

    // ---- coalesced write hs1 ----
#pragma unroll
    for (int i = 0; i < 8; i++) {
        int idx = tid + i * 256;             // 0..2047 float4s
        int row = idx >> 4, c4 = idx & 15;
        int grow = row0 + row;
        if (grow < N_NODES)
            *(float4*)&g_hs1[(size_t)grow * D_H + c4 * 4] =
                *(const float4*)&Ds[row * (A_STRIDE / 4) + c4 * 4];
    }
}

// ================= scale pass: hs1[n] *= rsqrt(deg_n) =================

__global__ __launch_bounds__(256) void k_scale() {
    int t = blockIdx.x * blockDim.x + threadIdx.x;
    int n = t >> 4;
    if (n >= N_NODES) return;
    float di = rsqrtf((float)g_cnt[n] + 1.0f);
    float4* p = (float4*)&g_hs1[(size_t)t * 4];
    float4 v = *p;
    v.x *= di; v.y *= di; v.z *= di; v.w *= di;
    *p = v;
}

// ====== fused layer-1 aggregation + relu + GEMV(W2) (proven R9 code) ======

__global__ __launch_bounds__(256) void k_agg_node(const float* __restrict__ b1,
                                                  const float* __restrict__ W2) {
    __shared__ float sh [16][68];
    __shared__ float W2t[16][68];

    const int tid  = threadIdx.x;
    const int part = tid & 15;
    const int nl   = tid >> 4;
    const int n    = blockIdx.x * 16 + nl;
    const int lane = tid & 31;
    const int gb   = lane & 16;
    const unsigned gmask = 0xFFFFu << gb;

#pragma unroll
    for (int idx = tid; idx < D_H * D_OUT; idx += 256) {
        int k = idx >> 4, j = idx & 15;
        W2t[j][k] = W2[idx];
    }

    const int cnt_n = g_cnt[n];
    int cnt = cnt_n > SLOT ? SLOT : cnt_n;
    const float dn = rsqrtf((float)cnt_n + 1.0f);
    const size_t off = (size_t)n * SLOT;

    const ulonglong2* base = (const ulonglong2*)g_hs1;
    ulonglong2 acc = base[(size_t)n * 16 + part];

    for (int i = 0; i < cnt; i += 16) {
        int idx = (i + part < cnt) ? g_csr[off + i + part] : 0;
#pragma unroll
        for (int j = 0; j < 16; j++) {
            int s = __shfl_sync(gmask, idx, gb + j);
            if (i + j < cnt) {
                ulonglong2 v = base[(size_t)s * 16 + part];
                FADD2(acc.x, acc.x, v.x);
                FADD2(acc.y, acc.y, v.y);
            }
        }
    }

    float a0, a1, a2, a3;
    unpack2(acc.x, a0, a1);
    unpack2(acc.y, a2, a3);
    float4 bb = *(const float4*)&b1[part * 4];
    float4 r;
    r.x = fmaxf(fmaf(dn, a0, bb.x), 0.f);
    r.y = fmaxf(fmaf(dn, a1, bb.y), 0.f);
    r.z = fmaxf(fmaf(dn, a2, bb.z), 0.f);
    r.w = fmaxf(fmaf(dn, a3, bb.w), 0.f);
    *(float4*)&sh[nl][part * 4] = r;
    __syncthreads();

    float o = 0.f;
#pragma unroll
    for (int k4 = 0; k4 < D_H / 4; k4++) {
        float4 v4 = *(const float4*)&sh [nl]  [k4 * 4];
        float4 w4 = *(const float4*)&W2t[part][k4 * 4];
        o = fmaf(v4.x, w4.x, o);
        o = fmaf(v4.y, w4.y, o);
        o = fmaf(v4.z, w4.z, o);
        o = fmaf(v4.w, w4.w, o);
    }
    g_hs2[(size_t)n * D_OUT + part] = o * dn;
}

// ====== layer-2 aggregation + epilogue; resets g_cnt (proven R9 code) ======

__global__ __launch_bounds__(256) void k_agg2(const float* __restrict__ b2,
                                              float* __restrict__ out) {
    long long t = (long long)blockIdx.x * blockDim.x + threadIdx.x;
    int n = (int)(t >> 2);
    const int valid = (n < N_NODES);
    if (!valid) n = N_NODES - 1;
    const int part = (int)(t & 3);
    const int lane = threadIdx.x & 31;
    const int gb4  = lane & ~3;
    const unsigned gmask = 0xFu << gb4;

    const int rawcnt = g_cnt[n];
    int cnt = rawcnt > SLOT ? SLOT : rawcnt;
    const size_t off = (size_t)n * SLOT;

    const ulonglong2* base = (const ulonglong2*)g_hs2;
    ulonglong2 acc = base[(size_t)n * 4 + part];

    for (int i = 0; i < cnt; i += 8) {
        int i0 = i + part;
        int i1 = i + 4 + part;
        int idxA = (i0 < cnt) ? g_csr[off + i0] : 0;
        int idxB = (i1 < cnt) ? g_csr[off + i1] : 0;
#pragma unroll
        for (int j = 0; j < 4; j++) {
            int s = __shfl_sync(gmask, idxA, gb4 + j);
            if (i + j < cnt) {
                ulonglong2 v = base[(size_t)s * 4 + part];
                FADD2(acc.x, acc.x, v.x);
                FADD2(acc.y, acc.y, v.y);
            }
        }
#pragma unroll
        for (int j = 0; j < 4; j++) {
            int s = __shfl_sync(gmask, idxB, gb4 + j);
            if (i + 4 + j < cnt) {
                ulonglong2 v = base[(size_t)s * 4 + part];
                FADD2(acc.x, acc.x, v.x);
                FADD2(acc.y, acc.y, v.y);
            }
        }
    }

    if (valid && part == 0) g_cnt[n] = 0;

    if (valid) {
        float a0, a1, a2, a3;
        unpack2(acc.x, a0, a1);
        unpack2(acc.y, a2, a3);
        float di = rsqrtf((float)rawcnt + 1.0f);
        float4 bb = *(const float4*)&b2[part * 4];
        float4 o = {fmaf(di, a0, bb.x), fmaf(di, a1, bb.y),
                    fmaf(di, a2, bb.z), fmaf(di, a3, bb.w)};
        *(float4*)&out[(size_t)n * D_OUT + part * 4] = o;
    }
}

// ================= launch =================

extern "C" void kernel_launch(void* const* d_in, const int* in_sizes, int n_in,
                              void* d_out, int out_size) {
    const float* x  = (const float*)d_in[0];
    const int*   ei = (const int*)  d_in[1];
    const float* W1 = (const float*)d_in[2];
    const float* b1 = (const float*)d_in[3];
    const float* W2 = (const float*)d_in[4];
    const float* b2 = (const float*)d_in[5];
    const int E = in_sizes[1] / 2;
    const int* src = ei;
    const int* dst = ei + E;

    static int smem_set = 0;
    if (!smem_set) {
        cudaFuncSetAttribute(k_fused, cudaFuncAttributeMaxDynamicSharedMemorySize, SMEM_TOTAL);
        smem_set = 1;
    }

    const int blocks = (N_NODES + 127) / 128;   // 782; 782*2048 >= E edges covered

    k_fused   <<<blocks, 256, SMEM_TOTAL>>>(x, W1, src, dst, E);
    k_scale   <<<(N_NODES * 16 + 255) / 256, 256>>>();
    k_agg_node<<<N_NODES / 16, 256>>>(b1, W2);
    k_agg2    <<<(N_NODES * 4 + 255) / 256, 256>>>(b2, (float*)d_out);
}